// round 5
// baseline (speedup 1.0000x reference)
#include <cuda_runtime.h>
#include <cstdint>
#include <cstddef>

// Problem constants
#define NB 4
#define NH 8
#define ND 64
#define NE 512
#define NR 512
#define NC 512

// Scratch (device globals; allocation inside kernel_launch is forbidden)
__device__ float g_Q[NB * NR * NE];
__device__ float g_K[NB * NC * NE];
__device__ float g_V[NB * NC * NE];
__device__ float g_logits[(size_t)NB * NH * NR * NC];  // dot -> weights (in place)
__device__ float g_attn[NB * NR * NE];
__device__ int   g_mask_is_i32;

// ---------------------------------------------------------------------------
// Probe mask dtype (bool-as-int32 vs uint8). Reads 256 bytes.
// ---------------------------------------------------------------------------
__global__ void detect_mask_kernel(const unsigned char* __restrict__ m)
{
    int is32 = 1;
    for (int i = 0; i < 256; i++)
        if ((i & 3) != 0 && m[i] != 0) { is32 = 0; break; }
    g_mask_is_i32 = is32;
}

// ---------------------------------------------------------------------------
// Fused Q/K/V projection: one launch, z selects (input, weight, output).
// C = A @ W^T, A:[2048,512], W:[512,512]. 64x64 tiles, 4x4 microtile,
// register-prefetched global loads.
// ---------------------------------------------------------------------------
__global__ __launch_bounds__(256) void qkv_gemm(
    const float* __restrict__ row_emb, const float* __restrict__ col_emb,
    const float* __restrict__ Wq, const float* __restrict__ Wk, const float* __restrict__ Wv,
    float* __restrict__ Qo, float* __restrict__ Ko, float* __restrict__ Vo)
{
    int z = blockIdx.z;
    const float* A = (z == 0) ? row_emb : col_emb;
    const float* B = (z == 0) ? Wq : (z == 1) ? Wk : Wv;
    float* C = (z == 0) ? Qo : (z == 1) ? Ko : Vo;

    __shared__ float As[16][68];
    __shared__ float Bs[16][68];

    int tid = threadIdx.x;
    int tx = tid & 15, ty = tid >> 4;
    int tm = blockIdx.y * 64, tn = blockIdx.x * 64;

    float acc[4][4];
#pragma unroll
    for (int i = 0; i < 4; i++)
#pragma unroll
        for (int j = 0; j < 4; j++) acc[i][j] = 0.0f;

    int lr = tid >> 2;
    int lk = (tid & 3) << 2;

    const float* aPtr = A + (size_t)(tm + lr) * NE + lk;
    const float* bPtr = B + (size_t)(tn + lr) * NE + lk;

    float4 av = *reinterpret_cast<const float4*>(aPtr);
    float4 bv = *reinterpret_cast<const float4*>(bPtr);

    for (int k0 = 0; k0 < NE; k0 += 16) {
        As[lk + 0][lr] = av.x; As[lk + 1][lr] = av.y; As[lk + 2][lr] = av.z; As[lk + 3][lr] = av.w;
        Bs[lk + 0][lr] = bv.x; Bs[lk + 1][lr] = bv.y; Bs[lk + 2][lr] = bv.z; Bs[lk + 3][lr] = bv.w;
        __syncthreads();
        if (k0 + 16 < NE) {
            av = *reinterpret_cast<const float4*>(aPtr + k0 + 16);
            bv = *reinterpret_cast<const float4*>(bPtr + k0 + 16);
        }
#pragma unroll
        for (int kk = 0; kk < 16; kk++) {
            float ar[4], br[4];
#pragma unroll
            for (int i = 0; i < 4; i++) ar[i] = As[kk][ty * 4 + i];
#pragma unroll
            for (int j = 0; j < 4; j++) br[j] = Bs[kk][tx * 4 + j];
#pragma unroll
            for (int i = 0; i < 4; i++)
#pragma unroll
                for (int j = 0; j < 4; j++) acc[i][j] = fmaf(ar[i], br[j], acc[i][j]);
        }
        __syncthreads();
    }

#pragma unroll
    for (int i = 0; i < 4; i++) {
        float4 o = make_float4(acc[i][0], acc[i][1], acc[i][2], acc[i][3]);
        *reinterpret_cast<float4*>(C + (size_t)(tm + ty * 4 + i) * NE + tn + tx * 4) = o;
    }
}

// ---------------------------------------------------------------------------
// C = alpha * A * B^T  (generic, z-batched, prefetched) — used for qk^T, outproj
// ---------------------------------------------------------------------------
__global__ __launch_bounds__(256) void sgemm_nt(
    const float* __restrict__ A, const float* __restrict__ B, float* __restrict__ C,
    int K, int lda, int ldb, int ldc,
    int inner, size_t aOut, size_t aIn, size_t bOut, size_t bIn, size_t cOut, size_t cIn,
    float alpha)
{
    int z = blockIdx.z;
    int zo = z / inner, zi = z - zo * inner;
    A += zo * aOut + zi * aIn;
    B += zo * bOut + zi * bIn;
    C += zo * cOut + zi * cIn;

    __shared__ float As[16][68];
    __shared__ float Bs[16][68];

    int tid = threadIdx.x;
    int tx = tid & 15, ty = tid >> 4;
    int tm = blockIdx.y * 64, tn = blockIdx.x * 64;

    float acc[4][4];
#pragma unroll
    for (int i = 0; i < 4; i++)
#pragma unroll
        for (int j = 0; j < 4; j++) acc[i][j] = 0.0f;

    int lr = tid >> 2;
    int lk = (tid & 3) << 2;

    const float* aPtr = A + (size_t)(tm + lr) * lda + lk;
    const float* bPtr = B + (size_t)(tn + lr) * ldb + lk;

    float4 av = *reinterpret_cast<const float4*>(aPtr);
    float4 bv = *reinterpret_cast<const float4*>(bPtr);

    for (int k0 = 0; k0 < K; k0 += 16) {
        As[lk + 0][lr] = av.x; As[lk + 1][lr] = av.y; As[lk + 2][lr] = av.z; As[lk + 3][lr] = av.w;
        Bs[lk + 0][lr] = bv.x; Bs[lk + 1][lr] = bv.y; Bs[lk + 2][lr] = bv.z; Bs[lk + 3][lr] = bv.w;
        __syncthreads();
        if (k0 + 16 < K) {
            av = *reinterpret_cast<const float4*>(aPtr + k0 + 16);
            bv = *reinterpret_cast<const float4*>(bPtr + k0 + 16);
        }
#pragma unroll
        for (int kk = 0; kk < 16; kk++) {
            float ar[4], br[4];
#pragma unroll
            for (int i = 0; i < 4; i++) ar[i] = As[kk][ty * 4 + i];
#pragma unroll
            for (int j = 0; j < 4; j++) br[j] = Bs[kk][tx * 4 + j];
#pragma unroll
            for (int i = 0; i < 4; i++)
#pragma unroll
                for (int j = 0; j < 4; j++) acc[i][j] = fmaf(ar[i], br[j], acc[i][j]);
        }
        __syncthreads();
    }

#pragma unroll
    for (int i = 0; i < 4; i++) {
        float4 o = make_float4(alpha * acc[i][0], alpha * acc[i][1],
                               alpha * acc[i][2], alpha * acc[i][3]);
        *reinterpret_cast<float4*>(C + (size_t)(tm + ty * 4 + i) * ldc + tn + tx * 4) = o;
    }
}

// ---------------------------------------------------------------------------
// C = A * B  (NN, z-batched, prefetched) — used for attn@V
// ---------------------------------------------------------------------------
__global__ __launch_bounds__(256) void sgemm_nn(
    const float* __restrict__ A, const float* __restrict__ B, float* __restrict__ C,
    int K, int lda, int ldb, int ldc,
    int inner, size_t aOut, size_t aIn, size_t bOut, size_t bIn, size_t cOut, size_t cIn)
{
    int z = blockIdx.z;
    int zo = z / inner, zi = z - zo * inner;
    A += zo * aOut + zi * aIn;
    B += zo * bOut + zi * bIn;
    C += zo * cOut + zi * cIn;

    __shared__ float As[16][68];
    __shared__ float Bs[16][68];

    int tid = threadIdx.x;
    int tx = tid & 15, ty = tid >> 4;
    int tm = blockIdx.y * 64, tn = blockIdx.x * 64;

    float acc[4][4];
#pragma unroll
    for (int i = 0; i < 4; i++)
#pragma unroll
        for (int j = 0; j < 4; j++) acc[i][j] = 0.0f;

    int lr = tid >> 2;        // A: tile row 0..63
    int lk = (tid & 3) << 2;  // A: k sub 0,4,8,12
    int kr = tid >> 4;        // B: k row 0..15
    int nb = (tid & 15) << 2; // B: n sub 0..60

    const float* aPtr = A + (size_t)(tm + lr) * lda + lk;
    const float* bPtr = B + (size_t)kr * ldb + tn + nb;

    float4 av = *reinterpret_cast<const float4*>(aPtr);
    float4 bv = *reinterpret_cast<const float4*>(bPtr);

    for (int k0 = 0; k0 < K; k0 += 16) {
        As[lk + 0][lr] = av.x; As[lk + 1][lr] = av.y; As[lk + 2][lr] = av.z; As[lk + 3][lr] = av.w;
        Bs[kr][nb + 0] = bv.x; Bs[kr][nb + 1] = bv.y; Bs[kr][nb + 2] = bv.z; Bs[kr][nb + 3] = bv.w;
        __syncthreads();
        if (k0 + 16 < K) {
            av = *reinterpret_cast<const float4*>(aPtr + k0 + 16);
            bv = *reinterpret_cast<const float4*>(bPtr + (size_t)(k0 + 16) * ldb);
        }
#pragma unroll
        for (int kk = 0; kk < 16; kk++) {
            float ar[4], br[4];
#pragma unroll
            for (int i = 0; i < 4; i++) ar[i] = As[kk][ty * 4 + i];
#pragma unroll
            for (int j = 0; j < 4; j++) br[j] = Bs[kk][tx * 4 + j];
#pragma unroll
            for (int i = 0; i < 4; i++)
#pragma unroll
                for (int j = 0; j < 4; j++) acc[i][j] = fmaf(ar[i], br[j], acc[i][j]);
        }
        __syncthreads();
    }

#pragma unroll
    for (int i = 0; i < 4; i++) {
        float4 o = make_float4(acc[i][0], acc[i][1], acc[i][2], acc[i][3]);
        *reinterpret_cast<float4*>(C + (size_t)(tm + ty * 4 + i) * ldc + tn + tx * 4) = o;
    }
}

// ---------------------------------------------------------------------------
// Fused mix-MLP + masked softmax. One block per (b,r); 128 threads x 4 cols.
// Block holds all 8 heads' logits for its (b,r) slice -> softmax rows are
// block-local. Reads dot from logits, writes final attention WEIGHTS in place.
//   hid_i = cost * (sum_h W1[i][2h+1]) + sum_h dot_h * W1[i][2h]; relu; @W2^T
//   then per-h: mask (-inf, with all-masked rows unmasked), softmax over c.
// ---------------------------------------------------------------------------
__global__ __launch_bounds__(128) void mix_softmax_kernel(
    const float* __restrict__ cost, const float* __restrict__ W1,
    const float* __restrict__ W2, float* __restrict__ logits,
    const void* __restrict__ maskv)
{
    __shared__ float w1e[128][8];
    __shared__ float w1o[128];
    __shared__ float w2s[8][128];
    __shared__ float red[4][8];
    __shared__ int   pall[4][8];

    int tx = threadIdx.x;
    int lane = tx & 31, wid = tx >> 5;
    {
        float s = 0.0f;
#pragma unroll
        for (int h = 0; h < 8; h++) {
            w1e[tx][h] = W1[tx * 16 + 2 * h];
            s += W1[tx * 16 + 2 * h + 1];
        }
        w1o[tx] = s;
#pragma unroll
        for (int j = 0; j < 8; j++) w2s[j][tx] = W2[j * 128 + tx];
    }
    __syncthreads();

    int br = blockIdx.x;
    int b = br >> 9;
    int r = br & 511;
    int c0 = tx * 4;

    // ---- mix MLP ----
    float dv[8][4];
#pragma unroll
    for (int h = 0; h < 8; h++) {
        float4 t = *reinterpret_cast<const float4*>(
            logits + (((size_t)(b * NH + h) * NR + r) * NC + c0));
        dv[h][0] = t.x; dv[h][1] = t.y; dv[h][2] = t.z; dv[h][3] = t.w;
    }
    float4 cvv = *reinterpret_cast<const float4*>(cost + ((size_t)b * NR + r) * NC + c0);
    float cw[4] = {cvv.x, cvv.y, cvv.z, cvv.w};

    float ms[4][8];
#pragma unroll
    for (int p = 0; p < 4; p++)
#pragma unroll
        for (int h = 0; h < 8; h++) ms[p][h] = 0.0f;

    for (int i = 0; i < 128; i++) {
        float wo = w1o[i];
        float h0 = cw[0] * wo, h1 = cw[1] * wo, h2 = cw[2] * wo, h3 = cw[3] * wo;
#pragma unroll
        for (int hh = 0; hh < 8; hh++) {
            float w = w1e[i][hh];
            h0 = fmaf(dv[hh][0], w, h0);
            h1 = fmaf(dv[hh][1], w, h1);
            h2 = fmaf(dv[hh][2], w, h2);
            h3 = fmaf(dv[hh][3], w, h3);
        }
        h0 = fmaxf(h0, 0.0f); h1 = fmaxf(h1, 0.0f); h2 = fmaxf(h2, 0.0f); h3 = fmaxf(h3, 0.0f);
#pragma unroll
        for (int hh = 0; hh < 8; hh++) {
            float w = w2s[hh][i];
            ms[0][hh] = fmaf(h0, w, ms[0][hh]);
            ms[1][hh] = fmaf(h1, w, ms[1][hh]);
            ms[2][hh] = fmaf(h2, w, ms[2][hh]);
            ms[3][hh] = fmaf(h3, w, ms[3][hh]);
        }
    }

    // ---- masks ----
    uchar4 mk[8];
    bool i32m = (g_mask_is_i32 != 0);
#pragma unroll
    for (int h = 0; h < 8; h++) {
        size_t ridx = ((size_t)(b * NH + h) * NR + r) * (NC / 4) + tx;
        if (i32m) {
            int4 t = reinterpret_cast<const int4*>(maskv)[ridx];
            mk[h] = make_uchar4(t.x != 0, t.y != 0, t.z != 0, t.w != 0);
        } else {
            mk[h] = reinterpret_cast<const uchar4*>(maskv)[ridx];
        }
    }

    // all-masked detection per head
#pragma unroll
    for (int h = 0; h < 8; h++) {
        bool mine_all = mk[h].x && mk[h].y && mk[h].z && mk[h].w;
        unsigned bal = __ballot_sync(0xffffffffu, mine_all);
        if (lane == 0) pall[wid][h] = (bal == 0xffffffffu) ? 1 : 0;
    }
    __syncthreads();
    bool am[8];
#pragma unroll
    for (int h = 0; h < 8; h++)
        am[h] = pall[0][h] && pall[1][h] && pall[2][h] && pall[3][h];
    __syncthreads();

    // apply mask
    const float NEG = __int_as_float(0xff800000);  // -inf
#pragma unroll
    for (int h = 0; h < 8; h++) {
        if (!am[h]) {
            if (mk[h].x) ms[0][h] = NEG;
            if (mk[h].y) ms[1][h] = NEG;
            if (mk[h].z) ms[2][h] = NEG;
            if (mk[h].w) ms[3][h] = NEG;
        }
    }

    // max reduction per head
#pragma unroll
    for (int h = 0; h < 8; h++) {
        float m = fmaxf(fmaxf(ms[0][h], ms[1][h]), fmaxf(ms[2][h], ms[3][h]));
#pragma unroll
        for (int s = 16; s > 0; s >>= 1) m = fmaxf(m, __shfl_xor_sync(0xffffffffu, m, s));
        if (lane == 0) red[wid][h] = m;
    }
    __syncthreads();
    float rmax[8];
#pragma unroll
    for (int h = 0; h < 8; h++)
        rmax[h] = fmaxf(fmaxf(red[0][h], red[1][h]), fmaxf(red[2][h], red[3][h]));
    __syncthreads();

    // exp + sum reduction per head
#pragma unroll
    for (int h = 0; h < 8; h++) {
        ms[0][h] = __expf(ms[0][h] - rmax[h]);
        ms[1][h] = __expf(ms[1][h] - rmax[h]);
        ms[2][h] = __expf(ms[2][h] - rmax[h]);
        ms[3][h] = __expf(ms[3][h] - rmax[h]);
        float sm = (ms[0][h] + ms[1][h]) + (ms[2][h] + ms[3][h]);
#pragma unroll
        for (int s = 16; s > 0; s >>= 1) sm += __shfl_xor_sync(0xffffffffu, sm, s);
        if (lane == 0) red[wid][h] = sm;
    }
    __syncthreads();

#pragma unroll
    for (int h = 0; h < 8; h++) {
        float inv = 1.0f / ((red[0][h] + red[1][h]) + (red[2][h] + red[3][h]));
        float4 o = make_float4(ms[0][h] * inv, ms[1][h] * inv, ms[2][h] * inv, ms[3][h] * inv);
        *reinterpret_cast<float4*>(logits + (((size_t)(b * NH + h) * NR + r) * NC + c0)) = o;
    }
}

// ---------------------------------------------------------------------------
extern "C" void kernel_launch(void* const* d_in, const int* in_sizes, int n_in,
                              void* d_out, int out_size)
{
    const float* row_emb = (const float*)d_in[0];
    const float* col_emb = (const float*)d_in[1];
    const float* cost    = (const float*)d_in[2];
    const void*  mask    = d_in[3];
    const float* Wq      = (const float*)d_in[4];
    const float* Wk      = (const float*)d_in[5];
    const float* Wv      = (const float*)d_in[6];
    const float* Wmix1   = (const float*)d_in[7];
    const float* Wmix2   = (const float*)d_in[8];
    const float* Wout    = (const float*)d_in[9];
    float* out = (float*)d_out;

    float *Q, *K, *V, *L, *AT;
    cudaGetSymbolAddress((void**)&Q,  g_Q);
    cudaGetSymbolAddress((void**)&K,  g_K);
    cudaGetSymbolAddress((void**)&V,  g_V);
    cudaGetSymbolAddress((void**)&L,  g_logits);
    cudaGetSymbolAddress((void**)&AT, g_attn);

    const size_t RE = (size_t)NR * NE;      // 262144
    const size_t RC = (size_t)NR * NC;      // 262144

    detect_mask_kernel<<<1, 1>>>((const unsigned char*)mask);

    // Q/K/V projections fused into one launch (768 CTAs)
    qkv_gemm<<<dim3(NE / 64, (NB * NR) / 64, 3), 256>>>(
        row_emb, col_emb, Wq, Wk, Wv, Q, K, V);

    // dot[b,h,r,c] = (1/8) * q . k   (batched over z = b*8+h)
    sgemm_nt<<<dim3(NC / 64, NR / 64, NB * NH), 256>>>(
        Q, K, L, ND, NE, NE, NC,
        NH, RE, (size_t)ND, RE, (size_t)ND, (size_t)NH * RC, RC,
        0.125f);

    // fused mix MLP + masked softmax (in place on L)
    mix_softmax_kernel<<<NB * NR, 128>>>(cost, Wmix1, Wmix2, L, mask);

    // attn @ V -> g_attn[b, r, h*64+d]
    sgemm_nn<<<dim3(1, NR / 64, NB * NH), 256>>>(
        L, V, AT, NC, NC, NE, NE,
        NH, (size_t)NH * RC, RC, (size_t)NC * NE, (size_t)ND, RE, (size_t)ND);

    // final projection: out = attn @ Wout^T
    sgemm_nt<<<dim3(NE / 64, (NB * NR) / 64, 1), 256>>>(
        AT, Wout, out, NE, NE, NE, NE,
        1, 0, 0, 0, 0, 0, 0, 1.0f);
}

// round 6
// speedup vs baseline: 1.3660x; 1.3660x over previous
#include <cuda_runtime.h>
#include <cstdint>
#include <cstddef>

// Problem constants
#define NB 4
#define NH 8
#define ND 64
#define NE 512
#define NR 512
#define NC 512

typedef unsigned long long u64;

// ---- packed f32x2 helpers (sm_103a) ----
__device__ __forceinline__ u64 pack2(float lo, float hi) {
    u64 r; asm("mov.b64 %0, {%1, %2};" : "=l"(r) : "f"(lo), "f"(hi)); return r;
}
__device__ __forceinline__ void unpack2(u64 v, float& lo, float& hi) {
    asm("mov.b64 {%0, %1}, %2;" : "=f"(lo), "=f"(hi) : "l"(v));
}
__device__ __forceinline__ void ffma2(u64& d, u64 a, u64 b) {
    asm("fma.rn.f32x2 %0, %1, %2, %0;" : "+l"(d) : "l"(a), "l"(b));
}
__device__ __forceinline__ u64 fmul2(u64 a, u64 b) {
    u64 r; asm("mul.rn.f32x2 %0, %1, %2;" : "=l"(r) : "l"(a), "l"(b)); return r;
}
__device__ __forceinline__ u64 fadd2(u64 a, u64 b) {
    u64 r; asm("add.rn.f32x2 %0, %1, %2;" : "=l"(r) : "l"(a), "l"(b)); return r;
}
__device__ __forceinline__ u64 relu2(u64 v) {
    float lo, hi; unpack2(v, lo, hi);
    return pack2(fmaxf(lo, 0.0f), fmaxf(hi, 0.0f));
}

// Scratch (device globals; allocation inside kernel_launch is forbidden)
__device__ float g_Q[NB * NR * NE];
__device__ float g_K[NB * NC * NE];
__device__ float g_V[NB * NC * NE];
__device__ float g_logits[(size_t)NB * NH * NR * NC];  // dot -> logits -> weights (in place)
__device__ float g_attn[NB * NR * NE];
__device__ int   g_mask_is_i32;

// ---------------------------------------------------------------------------
// Probe mask dtype (bool-as-int32 vs uint8). Reads 256 bytes.
// ---------------------------------------------------------------------------
__global__ void detect_mask_kernel(const unsigned char* __restrict__ m)
{
    int is32 = 1;
    for (int i = 0; i < 256; i++)
        if ((i & 3) != 0 && m[i] != 0) { is32 = 0; break; }
    g_mask_is_i32 = is32;
}

// ---------------------------------------------------------------------------
// C = alpha * A * B^T   (exact Round-3 body — known 46.1us/launch)
// ---------------------------------------------------------------------------
__global__ __launch_bounds__(256) void sgemm_nt(
    const float* __restrict__ A, const float* __restrict__ B, float* __restrict__ C,
    int M, int N, int K, int lda, int ldb, int ldc,
    int inner, size_t aOut, size_t aIn, size_t bOut, size_t bIn, size_t cOut, size_t cIn,
    float alpha)
{
    int z = blockIdx.z;
    int zo = z / inner, zi = z - zo * inner;
    A += zo * aOut + zi * aIn;
    B += zo * bOut + zi * bIn;
    C += zo * cOut + zi * cIn;

    __shared__ float As[16][68];
    __shared__ float Bs[16][68];

    int tid = threadIdx.x;
    int tx = tid & 15, ty = tid >> 4;
    int tm = blockIdx.y * 64, tn = blockIdx.x * 64;

    float acc[4][4];
#pragma unroll
    for (int i = 0; i < 4; i++)
#pragma unroll
        for (int j = 0; j < 4; j++) acc[i][j] = 0.0f;

    int lr = tid >> 2;         // 0..63 (tile row)
    int lk = (tid & 3) << 2;   // 0,4,8,12 (k sub-offset)

    for (int k0 = 0; k0 < K; k0 += 16) {
        float4 av = *reinterpret_cast<const float4*>(A + (size_t)(tm + lr) * lda + k0 + lk);
        float4 bv = *reinterpret_cast<const float4*>(B + (size_t)(tn + lr) * ldb + k0 + lk);
        As[lk + 0][lr] = av.x; As[lk + 1][lr] = av.y; As[lk + 2][lr] = av.z; As[lk + 3][lr] = av.w;
        Bs[lk + 0][lr] = bv.x; Bs[lk + 1][lr] = bv.y; Bs[lk + 2][lr] = bv.z; Bs[lk + 3][lr] = bv.w;
        __syncthreads();
#pragma unroll
        for (int kk = 0; kk < 16; kk++) {
            float ar[4], br[4];
#pragma unroll
            for (int i = 0; i < 4; i++) ar[i] = As[kk][ty * 4 + i];
#pragma unroll
            for (int j = 0; j < 4; j++) br[j] = Bs[kk][tx * 4 + j];
#pragma unroll
            for (int i = 0; i < 4; i++)
#pragma unroll
                for (int j = 0; j < 4; j++) acc[i][j] = fmaf(ar[i], br[j], acc[i][j]);
        }
        __syncthreads();
    }

#pragma unroll
    for (int i = 0; i < 4; i++)
#pragma unroll
        for (int j = 0; j < 4; j++)
            C[(size_t)(tm + ty * 4 + i) * ldc + tn + tx * 4 + j] = alpha * acc[i][j];
}

// ---------------------------------------------------------------------------
// C = A * B   (exact Round-3 body) — used for attn@V
// ---------------------------------------------------------------------------
__global__ __launch_bounds__(256) void sgemm_nn(
    const float* __restrict__ A, const float* __restrict__ B, float* __restrict__ C,
    int M, int N, int K, int lda, int ldb, int ldc,
    int inner, size_t aOut, size_t aIn, size_t bOut, size_t bIn, size_t cOut, size_t cIn)
{
    int z = blockIdx.z;
    int zo = z / inner, zi = z - zo * inner;
    A += zo * aOut + zi * aIn;
    B += zo * bOut + zi * bIn;
    C += zo * cOut + zi * cIn;

    __shared__ float As[16][68];
    __shared__ float Bs[16][68];

    int tid = threadIdx.x;
    int tx = tid & 15, ty = tid >> 4;
    int tm = blockIdx.y * 64, tn = blockIdx.x * 64;

    float acc[4][4];
#pragma unroll
    for (int i = 0; i < 4; i++)
#pragma unroll
        for (int j = 0; j < 4; j++) acc[i][j] = 0.0f;

    int lr = tid >> 2;        // A: tile row 0..63
    int lk = (tid & 3) << 2;  // A: k sub 0,4,8,12
    int kr = tid >> 4;        // B: k row 0..15
    int nb = (tid & 15) << 2; // B: n sub 0..60

    for (int k0 = 0; k0 < K; k0 += 16) {
        float4 av = *reinterpret_cast<const float4*>(A + (size_t)(tm + lr) * lda + k0 + lk);
        float4 bv = *reinterpret_cast<const float4*>(B + (size_t)(k0 + kr) * ldb + tn + nb);
        As[lk + 0][lr] = av.x; As[lk + 1][lr] = av.y; As[lk + 2][lr] = av.z; As[lk + 3][lr] = av.w;
        Bs[kr][nb + 0] = bv.x; Bs[kr][nb + 1] = bv.y; Bs[kr][nb + 2] = bv.z; Bs[kr][nb + 3] = bv.w;
        __syncthreads();
#pragma unroll
        for (int kk = 0; kk < 16; kk++) {
            float ar[4], br[4];
#pragma unroll
            for (int i = 0; i < 4; i++) ar[i] = As[kk][ty * 4 + i];
#pragma unroll
            for (int j = 0; j < 4; j++) br[j] = Bs[kk][tx * 4 + j];
#pragma unroll
            for (int i = 0; i < 4; i++)
#pragma unroll
                for (int j = 0; j < 4; j++) acc[i][j] = fmaf(ar[i], br[j], acc[i][j]);
        }
        __syncthreads();
    }

#pragma unroll
    for (int i = 0; i < 4; i++)
#pragma unroll
        for (int j = 0; j < 4; j++)
            C[(size_t)(tm + ty * 4 + i) * ldc + tn + tx * 4 + j] = acc[i][j];
}

// ---------------------------------------------------------------------------
// Mix MLP — packed f32x2 + vectorized weight loads.
//   hid_i = cost * (sum_h W1[i][2h+1]) + sum_h dot_h * W1[i][2h]; relu; @W2^T
// Weights in smem as {w,w} u64 pairs, per-i CONTIGUOUS so LDS.128 picks up 2
// at a time (broadcast across lanes -> conflict-free). Columns as 2 pairs.
// One block per (b,r); 128 threads x 4 columns. In place on g_logits.
// ---------------------------------------------------------------------------
__global__ __launch_bounds__(128) void mix_kernel(
    const float* __restrict__ cost, const float* __restrict__ W1,
    const float* __restrict__ W2, float* __restrict__ logits)
{
    __shared__ __align__(16) u64 w1e2[128][8];  // {w,w}, per-i contiguous
    __shared__ __align__(16) u64 w2t2[128][8];  // transposed W2: per-i contiguous
    __shared__ u64 w1o2[128];                   // {s,s} folded cost weight

    int tx = threadIdx.x;
    {
        float s = 0.0f;
#pragma unroll
        for (int h = 0; h < 8; h++) {
            float w = W1[tx * 16 + 2 * h];
            w1e2[tx][h] = pack2(w, w);
            s += W1[tx * 16 + 2 * h + 1];
        }
        w1o2[tx] = pack2(s, s);
#pragma unroll
        for (int j = 0; j < 8; j++) {
            float w = W2[j * 128 + tx];
            w2t2[tx][j] = pack2(w, w);
        }
    }
    __syncthreads();

    int br = blockIdx.x;
    int b = br >> 9;
    int r = br & 511;
    int c0 = tx * 4;

    u64 dv01[8], dv23[8];
#pragma unroll
    for (int h = 0; h < 8; h++) {
        float4 t = *reinterpret_cast<const float4*>(
            logits + (((size_t)(b * NH + h) * NR + r) * NC + c0));
        dv01[h] = pack2(t.x, t.y);
        dv23[h] = pack2(t.z, t.w);
    }
    float4 cvv = *reinterpret_cast<const float4*>(cost + ((size_t)b * NR + r) * NC + c0);
    u64 cw01 = pack2(cvv.x, cvv.y);
    u64 cw23 = pack2(cvv.z, cvv.w);

    u64 ms01[8], ms23[8];
#pragma unroll
    for (int h = 0; h < 8; h++) { ms01[h] = 0ull; ms23[h] = 0ull; }

    for (int i = 0; i < 128; i++) {
        u64 wo = w1o2[i];
        // stage 1: 4 dependency chains
        u64 ha01 = fmul2(cw01, wo), ha23 = fmul2(cw23, wo);
        u64 hb01 = 0ull, hb23 = 0ull;
#pragma unroll
        for (int hh = 0; hh < 4; hh++) {
            u64 w = w1e2[i][hh];
            ffma2(ha01, dv01[hh], w);
            ffma2(ha23, dv23[hh], w);
        }
#pragma unroll
        for (int hh = 4; hh < 8; hh++) {
            u64 w = w1e2[i][hh];
            ffma2(hb01, dv01[hh], w);
            ffma2(hb23, dv23[hh], w);
        }
        u64 h01 = relu2(fadd2(ha01, hb01));
        u64 h23 = relu2(fadd2(ha23, hb23));
#pragma unroll
        for (int hh = 0; hh < 8; hh++) {
            u64 w = w2t2[i][hh];
            ffma2(ms01[hh], h01, w);
            ffma2(ms23[hh], h23, w);
        }
    }

#pragma unroll
    for (int h = 0; h < 8; h++) {
        float m0, m1, m2, m3;
        unpack2(ms01[h], m0, m1);
        unpack2(ms23[h], m2, m3);
        float4 o = make_float4(m0, m1, m2, m3);
        *reinterpret_cast<float4*>(logits + (((size_t)(b * NH + h) * NR + r) * NC + c0)) = o;
    }
}

// ---------------------------------------------------------------------------
// Masked softmax (exact Round-3 body). Fully-masked rows become unmasked.
// ---------------------------------------------------------------------------
__global__ __launch_bounds__(128) void softmax_kernel(
    float* __restrict__ logits, const void* __restrict__ maskv)
{
    int row = blockIdx.x;
    float* lg = logits + (size_t)row * NC;
    int tx = threadIdx.x;
    int lane = tx & 31, wid = tx >> 5;

    float4 v = reinterpret_cast<const float4*>(lg)[tx];

    uchar4 mk;
    if (g_mask_is_i32) {
        int4 t = reinterpret_cast<const int4*>(maskv)[(size_t)row * (NC / 4) + tx];
        mk = make_uchar4(t.x != 0, t.y != 0, t.z != 0, t.w != 0);
    } else {
        mk = reinterpret_cast<const uchar4*>(maskv)[(size_t)row * (NC / 4) + tx];
    }

    __shared__ float pmax[4];
    __shared__ float psum[4];
    __shared__ int pall[4];

    bool mine_all = (mk.x != 0) && (mk.y != 0) && (mk.z != 0) && (mk.w != 0);
    unsigned bal = __ballot_sync(0xffffffffu, mine_all);
    if (lane == 0) pall[wid] = (bal == 0xffffffffu) ? 1 : 0;
    __syncthreads();
    bool am = pall[0] && pall[1] && pall[2] && pall[3];

    const float NEG = __int_as_float(0xff800000);  // -inf
    float x0 = (!am && mk.x) ? NEG : v.x;
    float x1 = (!am && mk.y) ? NEG : v.y;
    float x2 = (!am && mk.z) ? NEG : v.z;
    float x3 = (!am && mk.w) ? NEG : v.w;

    float m = fmaxf(fmaxf(x0, x1), fmaxf(x2, x3));
#pragma unroll
    for (int s = 16; s > 0; s >>= 1) m = fmaxf(m, __shfl_xor_sync(0xffffffffu, m, s));
    if (lane == 0) pmax[wid] = m;
    __syncthreads();
    float rmax = fmaxf(fmaxf(pmax[0], pmax[1]), fmaxf(pmax[2], pmax[3]));

    float e0 = __expf(x0 - rmax);
    float e1 = __expf(x1 - rmax);
    float e2 = __expf(x2 - rmax);
    float e3 = __expf(x3 - rmax);

    float sm = (e0 + e1) + (e2 + e3);
#pragma unroll
    for (int s = 16; s > 0; s >>= 1) sm += __shfl_xor_sync(0xffffffffu, sm, s);
    if (lane == 0) psum[wid] = sm;
    __syncthreads();
    float inv = 1.0f / (((psum[0] + psum[1]) + (psum[2] + psum[3])));

    float4 o = make_float4(e0 * inv, e1 * inv, e2 * inv, e3 * inv);
    reinterpret_cast<float4*>(lg)[tx] = o;
}

// ---------------------------------------------------------------------------
extern "C" void kernel_launch(void* const* d_in, const int* in_sizes, int n_in,
                              void* d_out, int out_size)
{
    const float* row_emb = (const float*)d_in[0];
    const float* col_emb = (const float*)d_in[1];
    const float* cost    = (const float*)d_in[2];
    const void*  mask    = d_in[3];
    const float* Wq      = (const float*)d_in[4];
    const float* Wk      = (const float*)d_in[5];
    const float* Wv      = (const float*)d_in[6];
    const float* Wmix1   = (const float*)d_in[7];
    const float* Wmix2   = (const float*)d_in[8];
    const float* Wout    = (const float*)d_in[9];
    float* out = (float*)d_out;

    float *Q, *K, *V, *L, *AT;
    cudaGetSymbolAddress((void**)&Q,  g_Q);
    cudaGetSymbolAddress((void**)&K,  g_K);
    cudaGetSymbolAddress((void**)&V,  g_V);
    cudaGetSymbolAddress((void**)&L,  g_logits);
    cudaGetSymbolAddress((void**)&AT, g_attn);

    const size_t RE = (size_t)NR * NE;      // 262144
    const size_t RC = (size_t)NR * NC;      // 262144

    detect_mask_kernel<<<1, 1>>>((const unsigned char*)mask);

    // Q/K/V projections: [2048,512] = emb @ W^T
    sgemm_nt<<<dim3(NE / 64, (NB * NR) / 64, 1), 256>>>(
        row_emb, Wq, Q, NB * NR, NE, NE, NE, NE, NE,
        1, 0, 0, 0, 0, 0, 0, 1.0f);
    sgemm_nt<<<dim3(NE / 64, (NB * NC) / 64, 1), 256>>>(
        col_emb, Wk, K, NB * NC, NE, NE, NE, NE, NE,
        1, 0, 0, 0, 0, 0, 0, 1.0f);
    sgemm_nt<<<dim3(NE / 64, (NB * NC) / 64, 1), 256>>>(
        col_emb, Wv, V, NB * NC, NE, NE, NE, NE, NE,
        1, 0, 0, 0, 0, 0, 0, 1.0f);

    // dot[b,h,r,c] = (1/8) * q . k   (batched over z = b*8+h)
    sgemm_nt<<<dim3(NC / 64, NR / 64, NB * NH), 256>>>(
        Q, K, L, NR, NC, ND, NE, NE, NC,
        NH, RE, (size_t)ND, RE, (size_t)ND, (size_t)NH * RC, RC,
        0.125f);

    // mix MLP (in place on L)
    mix_kernel<<<NB * NR, 128>>>(cost, Wmix1, Wmix2, L);

    // masked softmax (in place on L)
    softmax_kernel<<<NB * NH * NR, 128>>>(L, mask);

    // attn @ V -> g_attn[b, r, h*64+d]
    sgemm_nn<<<dim3(1, NR / 64, NB * NH), 256>>>(
        L, V, AT, NR, ND, NC, NC, NE, NE,
        NH, (size_t)NH * RC, RC, (size_t)NC * NE, (size_t)ND, RE, (size_t)ND);

    // final projection: out = attn @ Wout^T
    sgemm_nt<<<dim3(NE / 64, (NB * NR) / 64, 1), 256>>>(
        AT, Wout, out, NB * NR, NE, NE, NE, NE, NE,
        1, 0, 0, 0, 0, 0, 0, 1.0f);
}

// round 7
// speedup vs baseline: 1.5040x; 1.1010x over previous
#include <cuda_runtime.h>
#include <cstdint>
#include <cstddef>

// Problem constants
#define NB 4
#define NH 8
#define ND 64
#define NE 512
#define NR 512
#define NC 512

// Scratch (device globals; allocation inside kernel_launch is forbidden)
__device__ float g_Q[NB * NR * NE];
__device__ float g_K[NB * NC * NE];
__device__ float g_V[NB * NC * NE];
__device__ float g_logits[(size_t)NB * NH * NR * NC];  // dot -> logits -> weights (in place)
__device__ float g_attn[NB * NR * NE];
__device__ int   g_mask_is_i32;

// ---------------------------------------------------------------------------
// Probe mask dtype (bool-as-int32 vs uint8). Reads 256 bytes.
// ---------------------------------------------------------------------------
__global__ void detect_mask_kernel(const unsigned char* __restrict__ m)
{
    int is32 = 1;
    for (int i = 0; i < 256; i++)
        if ((i & 3) != 0 && m[i] != 0) { is32 = 0; break; }
    g_mask_is_i32 = is32;
}

// ---------------------------------------------------------------------------
// Fused Q/K/V projection. EXACT Round-3 sgemm_nt body; blockIdx.z in {0,1,2}
// selects (input, weight, output). One 768-CTA launch instead of 3x256.
// ---------------------------------------------------------------------------
__global__ __launch_bounds__(256) void qkv_gemm(
    const float* __restrict__ row_emb, const float* __restrict__ col_emb,
    const float* __restrict__ Wq, const float* __restrict__ Wk, const float* __restrict__ Wv,
    float* __restrict__ Qo, float* __restrict__ Ko, float* __restrict__ Vo)
{
    int z = blockIdx.z;
    const float* A = (z == 0) ? row_emb : col_emb;
    const float* B = (z == 0) ? Wq : (z == 1) ? Wk : Wv;
    float* C = (z == 0) ? Qo : (z == 1) ? Ko : Vo;

    __shared__ float As[16][68];
    __shared__ float Bs[16][68];

    int tid = threadIdx.x;
    int tx = tid & 15, ty = tid >> 4;
    int tm = blockIdx.y * 64, tn = blockIdx.x * 64;

    float acc[4][4];
#pragma unroll
    for (int i = 0; i < 4; i++)
#pragma unroll
        for (int j = 0; j < 4; j++) acc[i][j] = 0.0f;

    int lr = tid >> 2;         // 0..63 (tile row)
    int lk = (tid & 3) << 2;   // 0,4,8,12 (k sub-offset)

    for (int k0 = 0; k0 < NE; k0 += 16) {
        float4 av = *reinterpret_cast<const float4*>(A + (size_t)(tm + lr) * NE + k0 + lk);
        float4 bv = *reinterpret_cast<const float4*>(B + (size_t)(tn + lr) * NE + k0 + lk);
        As[lk + 0][lr] = av.x; As[lk + 1][lr] = av.y; As[lk + 2][lr] = av.z; As[lk + 3][lr] = av.w;
        Bs[lk + 0][lr] = bv.x; Bs[lk + 1][lr] = bv.y; Bs[lk + 2][lr] = bv.z; Bs[lk + 3][lr] = bv.w;
        __syncthreads();
#pragma unroll
        for (int kk = 0; kk < 16; kk++) {
            float ar[4], br[4];
#pragma unroll
            for (int i = 0; i < 4; i++) ar[i] = As[kk][ty * 4 + i];
#pragma unroll
            for (int j = 0; j < 4; j++) br[j] = Bs[kk][tx * 4 + j];
#pragma unroll
            for (int i = 0; i < 4; i++)
#pragma unroll
                for (int j = 0; j < 4; j++) acc[i][j] = fmaf(ar[i], br[j], acc[i][j]);
        }
        __syncthreads();
    }

#pragma unroll
    for (int i = 0; i < 4; i++)
#pragma unroll
        for (int j = 0; j < 4; j++)
            C[(size_t)(tm + ty * 4 + i) * NE + tn + tx * 4 + j] = acc[i][j];
}

// ---------------------------------------------------------------------------
// C = alpha * A * B^T   (exact Round-3 body)
// ---------------------------------------------------------------------------
__global__ __launch_bounds__(256) void sgemm_nt(
    const float* __restrict__ A, const float* __restrict__ B, float* __restrict__ C,
    int M, int N, int K, int lda, int ldb, int ldc,
    int inner, size_t aOut, size_t aIn, size_t bOut, size_t bIn, size_t cOut, size_t cIn,
    float alpha)
{
    int z = blockIdx.z;
    int zo = z / inner, zi = z - zo * inner;
    A += zo * aOut + zi * aIn;
    B += zo * bOut + zi * bIn;
    C += zo * cOut + zi * cIn;

    __shared__ float As[16][68];
    __shared__ float Bs[16][68];

    int tid = threadIdx.x;
    int tx = tid & 15, ty = tid >> 4;
    int tm = blockIdx.y * 64, tn = blockIdx.x * 64;

    float acc[4][4];
#pragma unroll
    for (int i = 0; i < 4; i++)
#pragma unroll
        for (int j = 0; j < 4; j++) acc[i][j] = 0.0f;

    int lr = tid >> 2;         // 0..63 (tile row)
    int lk = (tid & 3) << 2;   // 0,4,8,12 (k sub-offset)

    for (int k0 = 0; k0 < K; k0 += 16) {
        float4 av = *reinterpret_cast<const float4*>(A + (size_t)(tm + lr) * lda + k0 + lk);
        float4 bv = *reinterpret_cast<const float4*>(B + (size_t)(tn + lr) * ldb + k0 + lk);
        As[lk + 0][lr] = av.x; As[lk + 1][lr] = av.y; As[lk + 2][lr] = av.z; As[lk + 3][lr] = av.w;
        Bs[lk + 0][lr] = bv.x; Bs[lk + 1][lr] = bv.y; Bs[lk + 2][lr] = bv.z; Bs[lk + 3][lr] = bv.w;
        __syncthreads();
#pragma unroll
        for (int kk = 0; kk < 16; kk++) {
            float ar[4], br[4];
#pragma unroll
            for (int i = 0; i < 4; i++) ar[i] = As[kk][ty * 4 + i];
#pragma unroll
            for (int j = 0; j < 4; j++) br[j] = Bs[kk][tx * 4 + j];
#pragma unroll
            for (int i = 0; i < 4; i++)
#pragma unroll
                for (int j = 0; j < 4; j++) acc[i][j] = fmaf(ar[i], br[j], acc[i][j]);
        }
        __syncthreads();
    }

#pragma unroll
    for (int i = 0; i < 4; i++)
#pragma unroll
        for (int j = 0; j < 4; j++)
            C[(size_t)(tm + ty * 4 + i) * ldc + tn + tx * 4 + j] = alpha * acc[i][j];
}

// ---------------------------------------------------------------------------
// C = A * B   (exact Round-3 body) — used for attn@V
// ---------------------------------------------------------------------------
__global__ __launch_bounds__(256) void sgemm_nn(
    const float* __restrict__ A, const float* __restrict__ B, float* __restrict__ C,
    int M, int N, int K, int lda, int ldb, int ldc,
    int inner, size_t aOut, size_t aIn, size_t bOut, size_t bIn, size_t cOut, size_t cIn)
{
    int z = blockIdx.z;
    int zo = z / inner, zi = z - zo * inner;
    A += zo * aOut + zi * aIn;
    B += zo * bOut + zi * bIn;
    C += zo * cOut + zi * cIn;

    __shared__ float As[16][68];
    __shared__ float Bs[16][68];

    int tid = threadIdx.x;
    int tx = tid & 15, ty = tid >> 4;
    int tm = blockIdx.y * 64, tn = blockIdx.x * 64;

    float acc[4][4];
#pragma unroll
    for (int i = 0; i < 4; i++)
#pragma unroll
        for (int j = 0; j < 4; j++) acc[i][j] = 0.0f;

    int lr = tid >> 2;        // A: tile row 0..63
    int lk = (tid & 3) << 2;  // A: k sub 0,4,8,12
    int kr = tid >> 4;        // B: k row 0..15
    int nb = (tid & 15) << 2; // B: n sub 0..60

    for (int k0 = 0; k0 < K; k0 += 16) {
        float4 av = *reinterpret_cast<const float4*>(A + (size_t)(tm + lr) * lda + k0 + lk);
        float4 bv = *reinterpret_cast<const float4*>(B + (size_t)(k0 + kr) * ldb + tn + nb);
        As[lk + 0][lr] = av.x; As[lk + 1][lr] = av.y; As[lk + 2][lr] = av.z; As[lk + 3][lr] = av.w;
        Bs[kr][nb + 0] = bv.x; Bs[kr][nb + 1] = bv.y; Bs[kr][nb + 2] = bv.z; Bs[kr][nb + 3] = bv.w;
        __syncthreads();
#pragma unroll
        for (int kk = 0; kk < 16; kk++) {
            float ar[4], br[4];
#pragma unroll
            for (int i = 0; i < 4; i++) ar[i] = As[kk][ty * 4 + i];
#pragma unroll
            for (int j = 0; j < 4; j++) br[j] = Bs[kk][tx * 4 + j];
#pragma unroll
            for (int i = 0; i < 4; i++)
#pragma unroll
                for (int j = 0; j < 4; j++) acc[i][j] = fmaf(ar[i], br[j], acc[i][j]);
        }
        __syncthreads();
    }

#pragma unroll
    for (int i = 0; i < 4; i++)
#pragma unroll
        for (int j = 0; j < 4; j++)
            C[(size_t)(tm + ty * 4 + i) * ldc + tn + tx * 4 + j] = acc[i][j];
}

// ---------------------------------------------------------------------------
// Mix MLP (exact Round-3 scalar body).
//   hid_i = cost * (sum_h W1[i][2h+1]) + sum_h dot_h * W1[i][2h]; relu; @W2^T
// ---------------------------------------------------------------------------
__global__ __launch_bounds__(128) void mix_kernel(
    const float* __restrict__ cost, const float* __restrict__ W1,
    const float* __restrict__ W2, float* __restrict__ logits)
{
    __shared__ float w1e[128][8];
    __shared__ float w1o[128];
    __shared__ float w2s[8][128];

    int tx = threadIdx.x;
    {
        float s = 0.0f;
#pragma unroll
        for (int h = 0; h < 8; h++) {
            w1e[tx][h] = W1[tx * 16 + 2 * h];
            s += W1[tx * 16 + 2 * h + 1];
        }
        w1o[tx] = s;
#pragma unroll
        for (int j = 0; j < 8; j++) w2s[j][tx] = W2[j * 128 + tx];
    }
    __syncthreads();

    int br = blockIdx.x;
    int b = br >> 9;
    int r = br & 511;
    int c0 = tx * 4;

    float dv[8][4];
#pragma unroll
    for (int h = 0; h < 8; h++) {
        float4 t = *reinterpret_cast<const float4*>(
            logits + (((size_t)(b * NH + h) * NR + r) * NC + c0));
        dv[h][0] = t.x; dv[h][1] = t.y; dv[h][2] = t.z; dv[h][3] = t.w;
    }
    float4 cvv = *reinterpret_cast<const float4*>(cost + ((size_t)b * NR + r) * NC + c0);
    float cw[4] = {cvv.x, cvv.y, cvv.z, cvv.w};

    float ms[4][8];
#pragma unroll
    for (int p = 0; p < 4; p++)
#pragma unroll
        for (int h = 0; h < 8; h++) ms[p][h] = 0.0f;

    for (int i = 0; i < 128; i++) {
        float wo = w1o[i];
        float h0 = cw[0] * wo, h1 = cw[1] * wo, h2 = cw[2] * wo, h3 = cw[3] * wo;
#pragma unroll
        for (int hh = 0; hh < 8; hh++) {
            float w = w1e[i][hh];
            h0 = fmaf(dv[hh][0], w, h0);
            h1 = fmaf(dv[hh][1], w, h1);
            h2 = fmaf(dv[hh][2], w, h2);
            h3 = fmaf(dv[hh][3], w, h3);
        }
        h0 = fmaxf(h0, 0.0f); h1 = fmaxf(h1, 0.0f); h2 = fmaxf(h2, 0.0f); h3 = fmaxf(h3, 0.0f);
#pragma unroll
        for (int hh = 0; hh < 8; hh++) {
            float w = w2s[hh][i];
            ms[0][hh] = fmaf(h0, w, ms[0][hh]);
            ms[1][hh] = fmaf(h1, w, ms[1][hh]);
            ms[2][hh] = fmaf(h2, w, ms[2][hh]);
            ms[3][hh] = fmaf(h3, w, ms[3][hh]);
        }
    }

#pragma unroll
    for (int h = 0; h < 8; h++) {
        float4 o = make_float4(ms[0][h], ms[1][h], ms[2][h], ms[3][h]);
        *reinterpret_cast<float4*>(logits + (((size_t)(b * NH + h) * NR + r) * NC + c0)) = o;
    }
}

// ---------------------------------------------------------------------------
// Masked softmax (exact Round-3 body). Fully-masked rows become unmasked.
// ---------------------------------------------------------------------------
__global__ __launch_bounds__(128) void softmax_kernel(
    float* __restrict__ logits, const void* __restrict__ maskv)
{
    int row = blockIdx.x;
    float* lg = logits + (size_t)row * NC;
    int tx = threadIdx.x;
    int lane = tx & 31, wid = tx >> 5;

    float4 v = reinterpret_cast<const float4*>(lg)[tx];

    uchar4 mk;
    if (g_mask_is_i32) {
        int4 t = reinterpret_cast<const int4*>(maskv)[(size_t)row * (NC / 4) + tx];
        mk = make_uchar4(t.x != 0, t.y != 0, t.z != 0, t.w != 0);
    } else {
        mk = reinterpret_cast<const uchar4*>(maskv)[(size_t)row * (NC / 4) + tx];
    }

    __shared__ float pmax[4];
    __shared__ float psum[4];
    __shared__ int pall[4];

    bool mine_all = (mk.x != 0) && (mk.y != 0) && (mk.z != 0) && (mk.w != 0);
    unsigned bal = __ballot_sync(0xffffffffu, mine_all);
    if (lane == 0) pall[wid] = (bal == 0xffffffffu) ? 1 : 0;
    __syncthreads();
    bool am = pall[0] && pall[1] && pall[2] && pall[3];

    const float NEG = __int_as_float(0xff800000);  // -inf
    float x0 = (!am && mk.x) ? NEG : v.x;
    float x1 = (!am && mk.y) ? NEG : v.y;
    float x2 = (!am && mk.z) ? NEG : v.z;
    float x3 = (!am && mk.w) ? NEG : v.w;

    float m = fmaxf(fmaxf(x0, x1), fmaxf(x2, x3));
#pragma unroll
    for (int s = 16; s > 0; s >>= 1) m = fmaxf(m, __shfl_xor_sync(0xffffffffu, m, s));
    if (lane == 0) pmax[wid] = m;
    __syncthreads();
    float rmax = fmaxf(fmaxf(pmax[0], pmax[1]), fmaxf(pmax[2], pmax[3]));

    float e0 = __expf(x0 - rmax);
    float e1 = __expf(x1 - rmax);
    float e2 = __expf(x2 - rmax);
    float e3 = __expf(x3 - rmax);

    float sm = (e0 + e1) + (e2 + e3);
#pragma unroll
    for (int s = 16; s > 0; s >>= 1) sm += __shfl_xor_sync(0xffffffffu, sm, s);
    if (lane == 0) psum[wid] = sm;
    __syncthreads();
    float inv = 1.0f / (((psum[0] + psum[1]) + (psum[2] + psum[3])));

    float4 o = make_float4(e0 * inv, e1 * inv, e2 * inv, e3 * inv);
    reinterpret_cast<float4*>(lg)[tx] = o;
}

// ---------------------------------------------------------------------------
extern "C" void kernel_launch(void* const* d_in, const int* in_sizes, int n_in,
                              void* d_out, int out_size)
{
    const float* row_emb = (const float*)d_in[0];
    const float* col_emb = (const float*)d_in[1];
    const float* cost    = (const float*)d_in[2];
    const void*  mask    = d_in[3];
    const float* Wq      = (const float*)d_in[4];
    const float* Wk      = (const float*)d_in[5];
    const float* Wv      = (const float*)d_in[6];
    const float* Wmix1   = (const float*)d_in[7];
    const float* Wmix2   = (const float*)d_in[8];
    const float* Wout    = (const float*)d_in[9];
    float* out = (float*)d_out;

    float *Q, *K, *V, *L, *AT;
    cudaGetSymbolAddress((void**)&Q,  g_Q);
    cudaGetSymbolAddress((void**)&K,  g_K);
    cudaGetSymbolAddress((void**)&V,  g_V);
    cudaGetSymbolAddress((void**)&L,  g_logits);
    cudaGetSymbolAddress((void**)&AT, g_attn);

    const size_t RE = (size_t)NR * NE;      // 262144
    const size_t RC = (size_t)NR * NC;      // 262144

    detect_mask_kernel<<<1, 1>>>((const unsigned char*)mask);

    // Q/K/V projections fused into ONE launch (768 CTAs), R3 GEMM body
    qkv_gemm<<<dim3(NE / 64, (NB * NR) / 64, 3), 256>>>(
        row_emb, col_emb, Wq, Wk, Wv, Q, K, V);

    // dot[b,h,r,c] = (1/8) * q . k   (batched over z = b*8+h)
    sgemm_nt<<<dim3(NC / 64, NR / 64, NB * NH), 256>>>(
        Q, K, L, NR, NC, ND, NE, NE, NC,
        NH, RE, (size_t)ND, RE, (size_t)ND, (size_t)NH * RC, RC,
        0.125f);

    // mix MLP (in place on L)
    mix_kernel<<<NB * NR, 128>>>(cost, Wmix1, Wmix2, L);

    // masked softmax (in place on L)
    softmax_kernel<<<NB * NH * NR, 128>>>(L, mask);

    // attn @ V -> g_attn[b, r, h*64+d]
    sgemm_nn<<<dim3(1, NR / 64, NB * NH), 256>>>(
        L, V, AT, NR, ND, NC, NC, NE, NE,
        NH, (size_t)NH * RC, RC, (size_t)NC * NE, (size_t)ND, RE, (size_t)ND);

    // final projection: out = attn @ Wout^T
    sgemm_nt<<<dim3(NE / 64, (NB * NR) / 64, 1), 256>>>(
        AT, Wout, out, NB * NR, NE, NE, NE, NE, NE,
        1, 0, 0, 0, 0, 0, 0, 1.0f);
}